// round 16
// baseline (speedup 1.0000x reference)
#include <cuda_runtime.h>
#include <cuda_bf16.h>
#include <cstdint>
#include <math.h>

// Problem constants
#define BB 2
#define TT 2048
#define CC 2048
#define HH 16
#define DD 128
#define MM (BB * TT)    // 4096 rows
#define N3 (3 * CC)     // 6144

// Scratch (no cudaMalloc allowed)
__device__ float g_qkv[(size_t)MM * N3];                        // fp32 qkv
__device__ float g_y[(size_t)MM * CC];                          // fp32 attention out
__device__ __align__(16) __nv_bfloat16 g_ah[(size_t)MM * CC];   // A hi (x or y)
__device__ __align__(16) __nv_bfloat16 g_al[(size_t)MM * CC];   // A lo
__device__ __align__(16) __nv_bfloat16 g_bh[(size_t)N3 * CC];   // W^T hi
__device__ __align__(16) __nv_bfloat16 g_bl[(size_t)N3 * CC];   // W^T lo

// ---------------------------------------------------------------------------
// Base-target PTX helpers (NO tcgen05/TMEM — ptxas targets compute_103)
// ---------------------------------------------------------------------------
__device__ __forceinline__ uint32_t smem_u32(const void* p) {
    uint32_t a;
    asm("{ .reg .u64 t; cvta.to.shared.u64 t, %1; cvt.u32.u64 %0, t; }" : "=r"(a) : "l"(p));
    return a;
}

#define CP_ASYNC16(dst, src) asm volatile("cp.async.cg.shared.global [%0], [%1], 16;" :: "r"(dst), "l"(src))
#define CP_COMMIT()          asm volatile("cp.async.commit_group;" ::: "memory")
#define CP_WAIT0()           asm volatile("cp.async.wait_group 0;" ::: "memory")
#define CP_WAIT1()           asm volatile("cp.async.wait_group 1;" ::: "memory")

__device__ __forceinline__ void ldsm_x4(uint32_t* r, uint32_t addr) {
    asm volatile("ldmatrix.sync.aligned.m8n8.x4.shared.b16 {%0,%1,%2,%3}, [%4];"
                 : "=r"(r[0]), "=r"(r[1]), "=r"(r[2]), "=r"(r[3]) : "r"(addr));
}
__device__ __forceinline__ void ldsm_x4_t(uint32_t* r, uint32_t addr) {
    asm volatile("ldmatrix.sync.aligned.m8n8.x4.trans.shared.b16 {%0,%1,%2,%3}, [%4];"
                 : "=r"(r[0]), "=r"(r[1]), "=r"(r[2]), "=r"(r[3]) : "r"(addr));
}
__device__ __forceinline__ void mma16816(float* d, const uint32_t* a, const uint32_t* b) {
    asm volatile(
        "mma.sync.aligned.m16n8k16.row.col.f32.bf16.bf16.f32 "
        "{%0,%1,%2,%3}, {%4,%5,%6,%7}, {%8,%9}, {%0,%1,%2,%3};"
        : "+f"(d[0]), "+f"(d[1]), "+f"(d[2]), "+f"(d[3])
        : "r"(a[0]), "r"(a[1]), "r"(a[2]), "r"(a[3]), "r"(b[0]), "r"(b[1]));
}

// SW128 swizzle on byte offsets (128B rows)
#define SWZ(o) ((uint32_t)(o) ^ (((uint32_t)(o) >> 3) & 0x70u))

__device__ __forceinline__ uint32_t pack_bf2(float a, float b) {
    __nv_bfloat162 t = __floats2bfloat162_rn(a, b);
    return *reinterpret_cast<uint32_t*>(&t);
}

// Split a float4 into packed bf16 hi (uint2) and lo (uint2)
__device__ __forceinline__ void split4(float4 v, uint2& hi, uint2& lo) {
    __nv_bfloat16 h0 = __float2bfloat16_rn(v.x);
    __nv_bfloat16 h1 = __float2bfloat16_rn(v.y);
    __nv_bfloat16 h2 = __float2bfloat16_rn(v.z);
    __nv_bfloat16 h3 = __float2bfloat16_rn(v.w);
    __nv_bfloat162 a; a.x = h0; a.y = h1;
    __nv_bfloat162 b; b.x = h2; b.y = h3;
    hi.x = *reinterpret_cast<uint32_t*>(&a);
    hi.y = *reinterpret_cast<uint32_t*>(&b);
    lo.x = pack_bf2(v.x - __bfloat162float(h0), v.y - __bfloat162float(h1));
    lo.y = pack_bf2(v.z - __bfloat162float(h2), v.w - __bfloat162float(h3));
}

// ---------------------------------------------------------------------------
// Split kernels: fp32 -> bf16 hi + bf16 lo
// ---------------------------------------------------------------------------
__global__ void split_rm_kernel(const float* __restrict__ in,
                                __nv_bfloat16* __restrict__ oh,
                                __nv_bfloat16* __restrict__ ol, size_t n4)
{
    size_t i = (size_t)blockIdx.x * blockDim.x + threadIdx.x;
    if (i >= n4) return;
    float4 v = ((const float4*)in)[i];
    uint2 hi, lo;
    split4(v, hi, lo);
    ((uint2*)oh)[i] = hi;
    ((uint2*)ol)[i] = lo;
}

// W [Kd, Nd] fp32 -> out [Nd, Kd] bf16 hi/lo (transpose via smem tile)
__global__ void split_tr_kernel(const float* __restrict__ in,
                                __nv_bfloat16* __restrict__ oh,
                                __nv_bfloat16* __restrict__ ol, int Kd, int Nd)
{
    __shared__ float t[32][33];
    int n0 = blockIdx.x * 32, k0 = blockIdx.y * 32;
    int tx = threadIdx.x & 31, ty = threadIdx.x >> 5;   // 256 thr: ty 0..7
#pragma unroll
    for (int r = 0; r < 32; r += 8)
        t[ty + r][tx] = in[(size_t)(k0 + ty + r) * Nd + n0 + tx];
    __syncthreads();
#pragma unroll
    for (int r = 0; r < 32; r += 8) {
        int n = ty + r;
        float v = t[tx][n];
        __nv_bfloat16 h = __float2bfloat16_rn(v);
        __nv_bfloat16 l = __float2bfloat16_rn(v - __bfloat162float(h));
        oh[(size_t)(n0 + n) * Kd + k0 + tx] = h;
        ol[(size_t)(n0 + n) * Kd + k0 + tx] = l;
    }
}

// ---------------------------------------------------------------------------
// bf16-split GEMM via ldmatrix + mma.sync (m16n8k16)
// BM=128, BN=256, BK=32, 512 threads = 16 warps (2 x 8), warp tile 64x32.
// 3-stage cp.async pipeline; pass-major MMA ordering (16 indep chains/pass).
// ---------------------------------------------------------------------------
#define GBK 32
#define ATILE 16384                    // 128 rows * 128B
#define BTILE 32768                    // 256 rows * 128B
#define STAGE (ATILE + BTILE)          // 49152
#define G_SMEM (3 * STAGE)             // 147456
#define G_THREADS 512

__global__ __launch_bounds__(G_THREADS, 1)
void gemm_mma_kernel(const __nv_bfloat16* __restrict__ Ah,
                     const __nv_bfloat16* __restrict__ Al,
                     const __nv_bfloat16* __restrict__ Bh,
                     const __nv_bfloat16* __restrict__ Bl,
                     const float* __restrict__ bias,
                     float* __restrict__ Co, int Ndim, int Kdim)
{
    extern __shared__ char smem[];
    const uint32_t sb = smem_u32(smem);
    const int tid  = threadIdx.x;
    const int wid  = tid >> 5;
    const int lane = tid & 31;
    const int wm   = wid & 1;          // 2 M halves of 64
    const int wn   = wid >> 1;         // 8 N strips of 32
    const int row0 = blockIdx.y * 128;
    const int col0 = blockIdx.x * 256;

    const __nv_bfloat16* Ahp = Ah + (size_t)row0 * Kdim;
    const __nv_bfloat16* Alp = Al + (size_t)row0 * Kdim;
    const __nv_bfloat16* Bhp = Bh + (size_t)col0 * Kdim;
    const __nv_bfloat16* Blp = Bl + (size_t)col0 * Kdim;

    float acc[4][4][4];
#pragma unroll
    for (int i = 0; i < 4; i++)
#pragma unroll
        for (int j = 0; j < 4; j++)
#pragma unroll
            for (int k = 0; k < 4; k++) acc[i][j][k] = 0.0f;

    const int NCH = Kdim >> 5;

    // Stage layout: A rows 0..127 then B rows 0..255; row = [hi 64B | lo 64B]
    auto load_stage = [&](int s, int k0) {
        uint32_t st = sb + s * STAGE;
#pragma unroll
        for (int it = 0; it < 6; it++) {
            int i = tid + it * G_THREADS;      // 0..3071
            int r = i >> 3, c = i & 7;
            if (r < 128) {
                uint32_t d = SWZ(r * 128 + c * 16);
                const __nv_bfloat16* sa = (c < 4)
                    ? (Ahp + (size_t)r * Kdim + k0 + c * 8)
                    : (Alp + (size_t)r * Kdim + k0 + (c - 4) * 8);
                CP_ASYNC16(st + d, sa);
            } else {
                int rb = r - 128;
                uint32_t d = SWZ(rb * 128 + c * 16);
                const __nv_bfloat16* sbp = (c < 4)
                    ? (Bhp + (size_t)rb * Kdim + k0 + c * 8)
                    : (Blp + (size_t)rb * Kdim + k0 + (c - 4) * 8);
                CP_ASYNC16(st + ATILE + d, sbp);
            }
        }
    };

    // Prologue: two stages in flight
    load_stage(0, 0);
    CP_COMMIT();
    load_stage(1, GBK);
    CP_COMMIT();

    for (int ch = 0; ch < NCH; ch++) {
        CP_WAIT1();                     // stage ch landed
        __syncthreads();
        if (ch + 2 < NCH) load_stage((ch + 2) % 3, (ch + 2) * GBK);
        CP_COMMIT();

        const uint32_t as = sb + (ch % 3) * STAGE;
        const uint32_t bs = as + ATILE;

#pragma unroll
        for (int ks = 0; ks < 2; ks++) {
            uint32_t ah[4][4], al[4][4];
            {
                const int arow = wm * 64 + (lane & 15);
                const uint32_t kb = (uint32_t)(ks * 32 + ((lane >> 4) << 4));
#pragma unroll
                for (int mt = 0; mt < 4; mt++) {
                    uint32_t base = (uint32_t)((arow + mt * 16) * 128);
                    ldsm_x4(ah[mt], as + SWZ(base + kb));
                    ldsm_x4(al[mt], as + SWZ(base + kb + 64));
                }
            }
            uint32_t bh4[2][4], bl4[2][4];
            {
                const uint32_t rsel = (uint32_t)((lane & 7) + ((lane >> 4) << 3));
                const uint32_t kbB = (uint32_t)(ks * 32 + (((lane >> 3) & 1) << 4));
#pragma unroll
                for (int ntp = 0; ntp < 2; ntp++) {
                    uint32_t base = (uint32_t)((wn * 32 + ntp * 16 + rsel) * 128);
                    ldsm_x4(bh4[ntp], bs + SWZ(base + kbB));
                    ldsm_x4(bl4[ntp], bs + SWZ(base + kbB + 64));
                }
            }
            // Pass-major: 16 independent chains per pass
#pragma unroll
            for (int mt = 0; mt < 4; mt++)
#pragma unroll
                for (int ntp = 0; ntp < 2; ntp++) {
                    mma16816(acc[mt][2 * ntp],     ah[mt], &bh4[ntp][0]);
                    mma16816(acc[mt][2 * ntp + 1], ah[mt], &bh4[ntp][2]);
                }
#pragma unroll
            for (int mt = 0; mt < 4; mt++)
#pragma unroll
                for (int ntp = 0; ntp < 2; ntp++) {
                    mma16816(acc[mt][2 * ntp],     ah[mt], &bl4[ntp][0]);
                    mma16816(acc[mt][2 * ntp + 1], ah[mt], &bl4[ntp][2]);
                }
#pragma unroll
            for (int mt = 0; mt < 4; mt++)
#pragma unroll
                for (int ntp = 0; ntp < 2; ntp++) {
                    mma16816(acc[mt][2 * ntp],     al[mt], &bh4[ntp][0]);
                    mma16816(acc[mt][2 * ntp + 1], al[mt], &bh4[ntp][2]);
                }
        }
    }

    const int g = lane >> 2;
    const int cg = lane & 3;
#pragma unroll
    for (int mt = 0; mt < 4; mt++) {
#pragma unroll
        for (int nt = 0; nt < 4; nt++) {
            int row = row0 + wm * 64 + mt * 16 + g;
            int col = col0 + wn * 32 + nt * 8 + cg * 2;
            float b0 = __ldg(bias + col);
            float b1 = __ldg(bias + col + 1);
            float2 o0 = make_float2(acc[mt][nt][0] + b0, acc[mt][nt][1] + b1);
            float2 o1 = make_float2(acc[mt][nt][2] + b0, acc[mt][nt][3] + b1);
            *(float2*)(Co + (size_t)row * Ndim + col)       = o0;
            *(float2*)(Co + (size_t)(row + 8) * Ndim + col) = o1;
        }
    }
}

// ---------------------------------------------------------------------------
// Tensor-core causal flash attention: g_qkv -> g_y
// EXACT R9-passing version (388 us, 239 regs): BM=128, BN=64, 8 warps,
// x4-paired K/V fragment loads, reversed qt order for tail packing.
// ---------------------------------------------------------------------------
#define F_QH 0          // 2 panels * 16384
#define F_QL 32768
#define F_KH 65536      // 2 panels * 8192
#define F_KL 81920
#define F_VH 98304      // 2 panels * 8192
#define F_VL 114688
#define FLASH_SMEM 131072

__global__ __launch_bounds__(256, 1)
void flash_kernel()
{
    extern __shared__ char fsm[];
    const uint32_t sq = smem_u32(fsm);
    const int tid  = threadIdx.x;
    const int wid  = tid >> 5;
    const int lane = tid & 31;
    const int qt = gridDim.x - 1 - blockIdx.x;   // big tiles first
    const int h  = blockIdx.y;
    const int b  = blockIdx.z;
    const float scale = 0.08838834764831845f;  // 1/sqrt(128)

    const size_t base = ((size_t)b * TT) * N3 + (size_t)h * DD;
    const float* Qg = g_qkv + base;            // row stride N3
    const float* Kg = g_qkv + base + CC;
    const float* Vg = g_qkv + base + 2 * CC;
    const int q0 = qt * 128;

    // ---- Load Q tile (128 x 128) once: scale, split, swizzled panels ----
#pragma unroll
    for (int it = 0; it < 16; it++) {
        int idx = tid + it * 256;              // 0..4095
        int r = idx >> 5, c = idx & 31;        // r=q row, c=chunk of 4 d
        float4 v = *(const float4*)(Qg + (size_t)(q0 + r) * N3 + c * 4);
        v.x *= scale; v.y *= scale; v.z *= scale; v.w *= scale;
        uint2 hi, lo;
        split4(v, hi, lo);
        int p = c >> 4;
        uint32_t off = SWZ((uint32_t)(r * 128 + (c & 15) * 8));
        *(uint2*)(fsm + F_QH + p * 16384 + off) = hi;
        *(uint2*)(fsm + F_QL + p * 16384 + off) = lo;
    }

    // ---- State ----
    float o[16][4];
#pragma unroll
    for (int i = 0; i < 16; i++)
#pragma unroll
        for (int j = 0; j < 4; j++) o[i][j] = 0.0f;
    float m0 = -1e30f, m1 = -1e30f, l0 = 0.0f, l1 = 0.0f;

    const int nkt = 2 * qt + 2;

    for (int kt = 0; kt < nkt; kt++) {
        const int kk0 = kt * 64;
        __syncthreads();
        // ---- Load K, V tiles (64 x 128) ----
#pragma unroll
        for (int it = 0; it < 8; it++) {
            int idx = tid + it * 256;          // 0..2047
            int r = idx >> 5, c = idx & 31;
            int p = c >> 4;
            uint32_t off = SWZ((uint32_t)(r * 128 + (c & 15) * 8));
            float4 kv = *(const float4*)(Kg + (size_t)(kk0 + r) * N3 + c * 4);
            uint2 hi, lo;
            split4(kv, hi, lo);
            *(uint2*)(fsm + F_KH + p * 8192 + off) = hi;
            *(uint2*)(fsm + F_KL + p * 8192 + off) = lo;
            float4 vv = *(const float4*)(Vg + (size_t)(kk0 + r) * N3 + c * 4);
            split4(vv, hi, lo);
            *(uint2*)(fsm + F_VH + p * 8192 + off) = hi;
            *(uint2*)(fsm + F_VL + p * 8192 + off) = lo;
        }
        __syncthreads();

        // ---- S = Q @ K^T (3-pass split; x4-paired K frags) ----
        float s[8][4];
#pragma unroll
        for (int nt = 0; nt < 8; nt++)
#pragma unroll
            for (int j = 0; j < 4; j++) s[nt][j] = 0.0f;

#pragma unroll
        for (int ks = 0; ks < 8; ks++) {
            const int p = ks >> 2;
            uint32_t ah[4], al[4];
            {
                uint32_t kb = (uint32_t)((ks & 3) * 32 + ((lane >> 4) << 4));
                uint32_t aofs = (uint32_t)((wid * 16 + (lane & 15)) * 128) + kb;
                ldsm_x4(ah, sq + F_QH + p * 16384 + SWZ(aofs));
                ldsm_x4(al, sq + F_QL + p * 16384 + SWZ(aofs));
            }
            const uint32_t kb2 = (uint32_t)((ks & 3) * 32 + (((lane >> 3) & 1) << 4));
            const uint32_t rsel = (uint32_t)((lane & 7) + ((lane >> 4) << 3));
#pragma unroll
            for (int ntp = 0; ntp < 4; ntp++) {
                uint32_t bofs = (uint32_t)((ntp * 16 + rsel) * 128) + kb2;
                uint32_t bh4[4], bl4[4];
                ldsm_x4(bh4, sq + F_KH + p * 8192 + SWZ(bofs));
                ldsm_x4(bl4, sq + F_KL + p * 8192 + SWZ(bofs));
                mma16816(s[2 * ntp],     ah, &bh4[0]);
                mma16816(s[2 * ntp],     ah, &bl4[0]);
                mma16816(s[2 * ntp],     al, &bh4[0]);
                mma16816(s[2 * ntp + 1], ah, &bh4[2]);
                mma16816(s[2 * ntp + 1], ah, &bl4[2]);
                mma16816(s[2 * ntp + 1], al, &bh4[2]);
            }
        }

        // ---- Causal mask (only last two tiles can cross the diagonal) ----
        const int rg = q0 + wid * 16 + (lane >> 2);  // row of c0,c1; +8 for c2,c3
        if (kt >= 2 * qt) {
#pragma unroll
            for (int nt = 0; nt < 8; nt++) {
                int col = kk0 + nt * 8 + 2 * (lane & 3);
                if (col > rg)          s[nt][0] = -1e30f;
                if (col + 1 > rg)      s[nt][1] = -1e30f;
                if (col > rg + 8)      s[nt][2] = -1e30f;
                if (col + 1 > rg + 8)  s[nt][3] = -1e30f;
            }
        }

        // ---- Online softmax (rows rg and rg+8; quad-lane reductions) ----
        float mt0 = -1e30f, mt1 = -1e30f;
#pragma unroll
        for (int nt = 0; nt < 8; nt++) {
            mt0 = fmaxf(mt0, fmaxf(s[nt][0], s[nt][1]));
            mt1 = fmaxf(mt1, fmaxf(s[nt][2], s[nt][3]));
        }
        mt0 = fmaxf(mt0, __shfl_xor_sync(0xffffffffu, mt0, 1));
        mt0 = fmaxf(mt0, __shfl_xor_sync(0xffffffffu, mt0, 2));
        mt1 = fmaxf(mt1, __shfl_xor_sync(0xffffffffu, mt1, 1));
        mt1 = fmaxf(mt1, __shfl_xor_sync(0xffffffffu, mt1, 2));

        float mn0 = fmaxf(m0, mt0), mn1 = fmaxf(m1, mt1);
        float a0 = __expf(m0 - mn0), a1 = __expf(m1 - mn1);
        m0 = mn0; m1 = mn1;

        float rs0 = 0.0f, rs1 = 0.0f;
#pragma unroll
        for (int nt = 0; nt < 8; nt++) {
            s[nt][0] = __expf(s[nt][0] - mn0);
            s[nt][1] = __expf(s[nt][1] - mn0);
            s[nt][2] = __expf(s[nt][2] - mn1);
            s[nt][3] = __expf(s[nt][3] - mn1);
            rs0 += s[nt][0] + s[nt][1];
            rs1 += s[nt][2] + s[nt][3];
        }
        rs0 += __shfl_xor_sync(0xffffffffu, rs0, 1);
        rs0 += __shfl_xor_sync(0xffffffffu, rs0, 2);
        rs1 += __shfl_xor_sync(0xffffffffu, rs1, 1);
        rs1 += __shfl_xor_sync(0xffffffffu, rs1, 2);
        l0 = l0 * a0 + rs0;
        l1 = l1 * a1 + rs1;

#pragma unroll
        for (int dt = 0; dt < 16; dt++) {
            o[dt][0] *= a0; o[dt][1] *= a0;
            o[dt][2] *= a1; o[dt][3] *= a1;
        }

        // ---- O += P @ V (P from S regs; x4.trans-paired V frags) ----
#pragma unroll
        for (int ks2 = 0; ks2 < 4; ks2++) {
            const float* t0 = s[2 * ks2];
            const float* t1 = s[2 * ks2 + 1];
            uint32_t ph[4], pl[4];
            ph[0] = pack_bf2(t0[0], t0[1]);
            ph[1] = pack_bf2(t0[2], t0[3]);
            ph[2] = pack_bf2(t1[0], t1[1]);
            ph[3] = pack_bf2(t1[2], t1[3]);
            {
                __nv_bfloat162 hh;
                *reinterpret_cast<uint32_t*>(&hh) = ph[0];
                pl[0] = pack_bf2(t0[0] - __bfloat162float(hh.x), t0[1] - __bfloat162float(hh.y));
                *reinterpret_cast<uint32_t*>(&hh) = ph[1];
                pl[1] = pack_bf2(t0[2] - __bfloat162float(hh.x), t0[3] - __bfloat162float(hh.y));
                *reinterpret_cast<uint32_t*>(&hh) = ph[2];
                pl[2] = pack_bf2(t1[0] - __bfloat162float(hh.x), t1[1] - __bfloat162float(hh.y));
                *reinterpret_cast<uint32_t*>(&hh) = ph[3];
                pl[3] = pack_bf2(t1[2] - __bfloat162float(hh.x), t1[3] - __bfloat162float(hh.y));
            }
            uint32_t vrow = (uint32_t)((ks2 * 16 + (lane & 15)) * 128);
#pragma unroll
            for (int dtp = 0; dtp < 8; dtp++) {
                const int p = dtp >> 2;
                uint32_t colsel = (uint32_t)(((2 * dtp) & 7) + (lane >> 4));
                uint32_t bofs = vrow + colsel * 16;
                uint32_t vh4[4], vl4[4];
                ldsm_x4_t(vh4, sq + F_VH + p * 8192 + SWZ(bofs));
                ldsm_x4_t(vl4, sq + F_VL + p * 8192 + SWZ(bofs));
                mma16816(o[2 * dtp],     ph, &vh4[0]);
                mma16816(o[2 * dtp],     ph, &vl4[0]);
                mma16816(o[2 * dtp],     pl, &vh4[0]);
                mma16816(o[2 * dtp + 1], ph, &vh4[2]);
                mma16816(o[2 * dtp + 1], ph, &vl4[2]);
                mma16816(o[2 * dtp + 1], pl, &vh4[2]);
            }
        }
    }

    // ---- Normalize + write y [B,T,C] (head-interleaved cols) ----
    const float inv0 = 1.0f / l0;
    const float inv1 = 1.0f / l1;
    const int r0 = q0 + wid * 16 + (lane >> 2);
    float* y0 = g_y + ((size_t)b * TT + r0) * CC + (size_t)h * DD;
    float* y1 = g_y + ((size_t)b * TT + r0 + 8) * CC + (size_t)h * DD;
#pragma unroll
    for (int dt = 0; dt < 16; dt++) {
        int col = dt * 8 + 2 * (lane & 3);
        *(float2*)(y0 + col) = make_float2(o[dt][0] * inv0, o[dt][1] * inv0);
        *(float2*)(y1 + col) = make_float2(o[dt][2] * inv1, o[dt][3] * inv1);
    }
}

// ---------------------------------------------------------------------------
// Launch sequence
// ---------------------------------------------------------------------------
extern "C" void kernel_launch(void* const* d_in, const int* in_sizes, int n_in,
                              void* d_out, int out_size)
{
    (void)in_sizes; (void)n_in; (void)out_size;
    const float* x      = (const float*)d_in[0];
    const float* W_attn = (const float*)d_in[1];
    const float* b_attn = (const float*)d_in[2];
    const float* W_proj = (const float*)d_in[3];
    const float* b_proj = (const float*)d_in[4];
    float* out = (float*)d_out;

    float* qkv = nullptr; float* y = nullptr;
    __nv_bfloat16 *ah = nullptr, *al = nullptr, *bh = nullptr, *bl = nullptr;
    cudaGetSymbolAddress((void**)&qkv, g_qkv);
    cudaGetSymbolAddress((void**)&y,   g_y);
    cudaGetSymbolAddress((void**)&ah,  g_ah);
    cudaGetSymbolAddress((void**)&al,  g_al);
    cudaGetSymbolAddress((void**)&bh,  g_bh);
    cudaGetSymbolAddress((void**)&bl,  g_bl);

    cudaFuncSetAttribute(flash_kernel, cudaFuncAttributeMaxDynamicSharedMemorySize,
                         FLASH_SMEM);
    cudaFuncSetAttribute(gemm_mma_kernel, cudaFuncAttributeMaxDynamicSharedMemorySize,
                         (int)G_SMEM);

    const size_t n4 = (size_t)MM * CC / 4;

    // 1) QKV projection: bf16-split mma.sync GEMM (BN=256)
    split_rm_kernel<<<(unsigned)((n4 + 255) / 256), 256>>>(x, ah, al, n4);
    split_tr_kernel<<<dim3(N3 / 32, CC / 32), 256>>>(W_attn, bh, bl, CC, N3);
    gemm_mma_kernel<<<dim3(N3 / 256, MM / 128), G_THREADS, G_SMEM>>>(ah, al, bh, bl,
                                                                     b_attn, qkv, N3, CC);
    // 2) Causal multi-head attention (tensor-core flash)
    flash_kernel<<<dim3(TT / 128, HH, BB), 256, FLASH_SMEM>>>();

    // 3) Output projection: bf16-split mma.sync GEMM (BN=256)
    split_rm_kernel<<<(unsigned)((n4 + 255) / 256), 256>>>(y, ah, al, n4);
    split_tr_kernel<<<dim3(CC / 32, CC / 32), 256>>>(W_proj, bh, bl, CC, CC);
    gemm_mma_kernel<<<dim3(CC / 256, MM / 128), G_THREADS, G_SMEM>>>(ah, al, bh, bl,
                                                                     b_proj, out, CC, CC);
}

// round 17
// speedup vs baseline: 1.0311x; 1.0311x over previous
#include <cuda_runtime.h>
#include <cuda_bf16.h>
#include <cstdint>
#include <math.h>

// Problem constants
#define BB 2
#define TT 2048
#define CC 2048
#define HH 16
#define DD 128
#define MM (BB * TT)    // 4096 rows
#define N3 (3 * CC)     // 6144

// Scratch (no cudaMalloc allowed)
__device__ float g_qkv[(size_t)MM * N3];                        // fp32 qkv
__device__ float g_y[(size_t)MM * CC];                          // fp32 attention out
__device__ __align__(16) __nv_bfloat16 g_ah[(size_t)MM * CC];   // A hi (x or y)
__device__ __align__(16) __nv_bfloat16 g_al[(size_t)MM * CC];   // A lo
__device__ __align__(16) __nv_bfloat16 g_bh[(size_t)N3 * CC];   // W^T hi
__device__ __align__(16) __nv_bfloat16 g_bl[(size_t)N3 * CC];   // W^T lo

// ---------------------------------------------------------------------------
// Base-target PTX helpers (NO tcgen05/TMEM — ptxas targets compute_103)
// ---------------------------------------------------------------------------
__device__ __forceinline__ uint32_t smem_u32(const void* p) {
    uint32_t a;
    asm("{ .reg .u64 t; cvta.to.shared.u64 t, %1; cvt.u32.u64 %0, t; }" : "=r"(a) : "l"(p));
    return a;
}

#define CP_ASYNC16(dst, src) asm volatile("cp.async.cg.shared.global [%0], [%1], 16;" :: "r"(dst), "l"(src))
#define CP_COMMIT()          asm volatile("cp.async.commit_group;" ::: "memory")
#define CP_WAIT0()           asm volatile("cp.async.wait_group 0;" ::: "memory")
#define CP_WAIT1()           asm volatile("cp.async.wait_group 1;" ::: "memory")

__device__ __forceinline__ void ldsm_x4(uint32_t* r, uint32_t addr) {
    asm volatile("ldmatrix.sync.aligned.m8n8.x4.shared.b16 {%0,%1,%2,%3}, [%4];"
                 : "=r"(r[0]), "=r"(r[1]), "=r"(r[2]), "=r"(r[3]) : "r"(addr));
}
__device__ __forceinline__ void ldsm_x4_t(uint32_t* r, uint32_t addr) {
    asm volatile("ldmatrix.sync.aligned.m8n8.x4.trans.shared.b16 {%0,%1,%2,%3}, [%4];"
                 : "=r"(r[0]), "=r"(r[1]), "=r"(r[2]), "=r"(r[3]) : "r"(addr));
}
__device__ __forceinline__ void mma16816(float* d, const uint32_t* a, const uint32_t* b) {
    asm volatile(
        "mma.sync.aligned.m16n8k16.row.col.f32.bf16.bf16.f32 "
        "{%0,%1,%2,%3}, {%4,%5,%6,%7}, {%8,%9}, {%0,%1,%2,%3};"
        : "+f"(d[0]), "+f"(d[1]), "+f"(d[2]), "+f"(d[3])
        : "r"(a[0]), "r"(a[1]), "r"(a[2]), "r"(a[3]), "r"(b[0]), "r"(b[1]));
}

// SW128 swizzle on byte offsets (128B rows)
#define SWZ(o) ((uint32_t)(o) ^ (((uint32_t)(o) >> 3) & 0x70u))

__device__ __forceinline__ uint32_t pack_bf2(float a, float b) {
    __nv_bfloat162 t = __floats2bfloat162_rn(a, b);
    return *reinterpret_cast<uint32_t*>(&t);
}

// Split a float4 into packed bf16 hi (uint2) and lo (uint2)
__device__ __forceinline__ void split4(float4 v, uint2& hi, uint2& lo) {
    __nv_bfloat16 h0 = __float2bfloat16_rn(v.x);
    __nv_bfloat16 h1 = __float2bfloat16_rn(v.y);
    __nv_bfloat16 h2 = __float2bfloat16_rn(v.z);
    __nv_bfloat16 h3 = __float2bfloat16_rn(v.w);
    __nv_bfloat162 a; a.x = h0; a.y = h1;
    __nv_bfloat162 b; b.x = h2; b.y = h3;
    hi.x = *reinterpret_cast<uint32_t*>(&a);
    hi.y = *reinterpret_cast<uint32_t*>(&b);
    lo.x = pack_bf2(v.x - __bfloat162float(h0), v.y - __bfloat162float(h1));
    lo.y = pack_bf2(v.z - __bfloat162float(h2), v.w - __bfloat162float(h3));
}

// ---------------------------------------------------------------------------
// Split kernels: fp32 -> bf16 hi + bf16 lo
// ---------------------------------------------------------------------------
__global__ void split_rm_kernel(const float* __restrict__ in,
                                __nv_bfloat16* __restrict__ oh,
                                __nv_bfloat16* __restrict__ ol, size_t n4)
{
    size_t i = (size_t)blockIdx.x * blockDim.x + threadIdx.x;
    if (i >= n4) return;
    float4 v = ((const float4*)in)[i];
    uint2 hi, lo;
    split4(v, hi, lo);
    ((uint2*)oh)[i] = hi;
    ((uint2*)ol)[i] = lo;
}

// W [Kd, Nd] fp32 -> out [Nd, Kd] bf16 hi/lo (transpose via smem tile)
__global__ void split_tr_kernel(const float* __restrict__ in,
                                __nv_bfloat16* __restrict__ oh,
                                __nv_bfloat16* __restrict__ ol, int Kd, int Nd)
{
    __shared__ float t[32][33];
    int n0 = blockIdx.x * 32, k0 = blockIdx.y * 32;
    int tx = threadIdx.x & 31, ty = threadIdx.x >> 5;   // 256 thr: ty 0..7
#pragma unroll
    for (int r = 0; r < 32; r += 8)
        t[ty + r][tx] = in[(size_t)(k0 + ty + r) * Nd + n0 + tx];
    __syncthreads();
#pragma unroll
    for (int r = 0; r < 32; r += 8) {
        int n = ty + r;
        float v = t[tx][n];
        __nv_bfloat16 h = __float2bfloat16_rn(v);
        __nv_bfloat16 l = __float2bfloat16_rn(v - __bfloat162float(h));
        oh[(size_t)(n0 + n) * Kd + k0 + tx] = h;
        ol[(size_t)(n0 + n) * Kd + k0 + tx] = l;
    }
}

// ---------------------------------------------------------------------------
// bf16-split GEMM via ldmatrix + mma.sync (m16n8k16)
// BM=BN=128, BK=64 (2 sub-chunks of 32), 256 threads = 8 warps (2x4).
// 3-stage cp.async pipeline; halved sync/wait boundaries vs BK=32.
// Inner fragment/MMA code identical to the 1630us-benched version.
// ---------------------------------------------------------------------------
#define GBK 64
#define SUBCH 32768                    // per 32-k sub-chunk: A 16KB + B 16KB
#define STAGE (2 * SUBCH)              // 65536
#define G_SMEM (3 * STAGE)             // 196608

__global__ __launch_bounds__(256, 1)
void gemm_mma_kernel(const __nv_bfloat16* __restrict__ Ah,
                     const __nv_bfloat16* __restrict__ Al,
                     const __nv_bfloat16* __restrict__ Bh,
                     const __nv_bfloat16* __restrict__ Bl,
                     const float* __restrict__ bias,
                     float* __restrict__ Co, int Ndim, int Kdim)
{
    extern __shared__ char smem[];
    const uint32_t sb = smem_u32(smem);
    const int tid  = threadIdx.x;
    const int wid  = tid >> 5;
    const int lane = tid & 31;
    const int wm   = wid & 1;
    const int wn   = wid >> 1;
    const int row0 = blockIdx.y * 128;
    const int col0 = blockIdx.x * 128;

    const __nv_bfloat16* Ahp = Ah + (size_t)row0 * Kdim;
    const __nv_bfloat16* Alp = Al + (size_t)row0 * Kdim;
    const __nv_bfloat16* Bhp = Bh + (size_t)col0 * Kdim;
    const __nv_bfloat16* Blp = Bl + (size_t)col0 * Kdim;

    float acc[4][4][4];
#pragma unroll
    for (int i = 0; i < 4; i++)
#pragma unroll
        for (int j = 0; j < 4; j++)
#pragma unroll
            for (int k = 0; k < 4; k++) acc[i][j][k] = 0.0f;

    const int NCH = Kdim >> 6;         // 64-wide K chunks (32 for K=2048)

    // Stage = two 32-k sub-chunks, each [A 128x(hi64B|lo64B) | B same]
    auto load_stage = [&](int s, int k0) {
        uint32_t st = sb + s * STAGE;
#pragma unroll
        for (int half = 0; half < 2; half++) {
            const int kk = k0 + half * 32;
            uint32_t hb = st + half * SUBCH;
#pragma unroll
            for (int it = 0; it < 4; it++) {
                int i = tid + it * 256;
                int r = i >> 3, c = i & 7;
                uint32_t d = SWZ(r * 128 + c * 16);
                const __nv_bfloat16* sa = (c < 4)
                    ? (Ahp + (size_t)r * Kdim + kk + c * 8)
                    : (Alp + (size_t)r * Kdim + kk + (c - 4) * 8);
                CP_ASYNC16(hb + d, sa);
                const __nv_bfloat16* sbp = (c < 4)
                    ? (Bhp + (size_t)r * Kdim + kk + c * 8)
                    : (Blp + (size_t)r * Kdim + kk + (c - 4) * 8);
                CP_ASYNC16(hb + 16384 + d, sbp);
            }
        }
    };

    // Prologue: two stages in flight
    load_stage(0, 0);
    CP_COMMIT();
    load_stage(1, GBK);
    CP_COMMIT();

    for (int ch = 0; ch < NCH; ch++) {
        CP_WAIT1();                     // stage ch landed
        __syncthreads();
        if (ch + 2 < NCH) load_stage((ch + 2) % 3, (ch + 2) * GBK);
        CP_COMMIT();

#pragma unroll
        for (int sub = 0; sub < 2; sub++) {
            const uint32_t as = sb + (ch % 3) * STAGE + sub * SUBCH;
            const uint32_t bs = as + 16384;

#pragma unroll
            for (int ks = 0; ks < 2; ks++) {
                uint32_t ah[4][4], al[4][4];
                {
                    const int arow = wm * 64 + (lane & 15);
                    const uint32_t kb = (uint32_t)(ks * 32 + ((lane >> 4) << 4));
#pragma unroll
                    for (int mt = 0; mt < 4; mt++) {
                        uint32_t base = (uint32_t)((arow + mt * 16) * 128);
                        ldsm_x4(ah[mt], as + SWZ(base + kb));
                        ldsm_x4(al[mt], as + SWZ(base + kb + 64));
                    }
                }
                uint32_t bh4[2][4], bl4[2][4];
                {
                    const uint32_t rsel = (uint32_t)((lane & 7) + ((lane >> 4) << 3));
                    const uint32_t kbB = (uint32_t)(ks * 32 + (((lane >> 3) & 1) << 4));
#pragma unroll
                    for (int ntp = 0; ntp < 2; ntp++) {
                        uint32_t base = (uint32_t)((wn * 32 + ntp * 16 + rsel) * 128);
                        ldsm_x4(bh4[ntp], bs + SWZ(base + kbB));
                        ldsm_x4(bl4[ntp], bs + SWZ(base + kbB + 64));
                    }
                }
#pragma unroll
                for (int mt = 0; mt < 4; mt++)
#pragma unroll
                    for (int ntp = 0; ntp < 2; ntp++) {
                        mma16816(acc[mt][2 * ntp],     ah[mt], &bh4[ntp][0]);
                        mma16816(acc[mt][2 * ntp],     ah[mt], &bl4[ntp][0]);
                        mma16816(acc[mt][2 * ntp],     al[mt], &bh4[ntp][0]);
                        mma16816(acc[mt][2 * ntp + 1], ah[mt], &bh4[ntp][2]);
                        mma16816(acc[mt][2 * ntp + 1], ah[mt], &bl4[ntp][2]);
                        mma16816(acc[mt][2 * ntp + 1], al[mt], &bh4[ntp][2]);
                    }
            }
        }
    }

    const int g = lane >> 2;
    const int cg = lane & 3;
#pragma unroll
    for (int mt = 0; mt < 4; mt++) {
#pragma unroll
        for (int nt = 0; nt < 4; nt++) {
            int row = row0 + wm * 64 + mt * 16 + g;
            int col = col0 + wn * 32 + nt * 8 + cg * 2;
            float b0 = __ldg(bias + col);
            float b1 = __ldg(bias + col + 1);
            float2 o0 = make_float2(acc[mt][nt][0] + b0, acc[mt][nt][1] + b1);
            float2 o1 = make_float2(acc[mt][nt][2] + b0, acc[mt][nt][3] + b1);
            *(float2*)(Co + (size_t)row * Ndim + col)       = o0;
            *(float2*)(Co + (size_t)(row + 8) * Ndim + col) = o1;
        }
    }
}

// ---------------------------------------------------------------------------
// Tensor-core causal flash attention: g_qkv -> g_y
// R9-passing compute core + cp.async fp32 K/V staging: global fetch of tile
// t+1 overlaps all MMA work on tile t; convert reads smem (LDS) not global.
// ---------------------------------------------------------------------------
#define F_QH 0          // 2 panels * 16384
#define F_QL 32768
#define F_KH 65536      // 2 panels * 8192
#define F_KL 81920
#define F_VH 98304      // 2 panels * 8192
#define F_VL 114688
#define F_ST 131072     // fp32 stage: K 32KB + V 32KB
#define FLASH_SMEM 196608

__global__ __launch_bounds__(256, 1)
void flash_kernel()
{
    extern __shared__ char fsm[];
    const uint32_t sq = smem_u32(fsm);
    const int tid  = threadIdx.x;
    const int wid  = tid >> 5;
    const int lane = tid & 31;
    const int qt = gridDim.x - 1 - blockIdx.x;   // big tiles first
    const int h  = blockIdx.y;
    const int b  = blockIdx.z;
    const float scale = 0.08838834764831845f;  // 1/sqrt(128)

    const size_t base = ((size_t)b * TT) * N3 + (size_t)h * DD;
    const float* Qg = g_qkv + base;            // row stride N3
    const float* Kg = g_qkv + base + CC;
    const float* Vg = g_qkv + base + 2 * CC;
    const int q0 = qt * 128;

    const int nkt = 2 * qt + 2;

    // Stage fetch for k-tile kt: fp32 K rows then V rows, 512B linear rows.
    auto fetch_kv = [&](int kt) {
        const int kk0 = kt * 64;
#pragma unroll
        for (int it = 0; it < 8; it++) {
            int idx = tid + it * 256;          // 0..2047
            int r = idx >> 5, c = idx & 31;
            uint32_t d = (uint32_t)(F_ST + r * 512 + c * 16);
            CP_ASYNC16(sq + d,         Kg + (size_t)(kk0 + r) * N3 + c * 4);
            CP_ASYNC16(sq + d + 32768, Vg + (size_t)(kk0 + r) * N3 + c * 4);
        }
    };

    // Prologue: start fetching k-tile 0 immediately, then load Q.
    fetch_kv(0);
    CP_COMMIT();

    // ---- Load Q tile (128 x 128) once: scale, split, swizzled panels ----
#pragma unroll
    for (int it = 0; it < 16; it++) {
        int idx = tid + it * 256;              // 0..4095
        int r = idx >> 5, c = idx & 31;        // r=q row, c=chunk of 4 d
        float4 v = *(const float4*)(Qg + (size_t)(q0 + r) * N3 + c * 4);
        v.x *= scale; v.y *= scale; v.z *= scale; v.w *= scale;
        uint2 hi, lo;
        split4(v, hi, lo);
        int p = c >> 4;
        uint32_t off = SWZ((uint32_t)(r * 128 + (c & 15) * 8));
        *(uint2*)(fsm + F_QH + p * 16384 + off) = hi;
        *(uint2*)(fsm + F_QL + p * 16384 + off) = lo;
    }

    // ---- State ----
    float o[16][4];
#pragma unroll
    for (int i = 0; i < 16; i++)
#pragma unroll
        for (int j = 0; j < 4; j++) o[i][j] = 0.0f;
    float m0 = -1e30f, m1 = -1e30f, l0 = 0.0f, l1 = 0.0f;

    for (int kt = 0; kt < nkt; kt++) {
        const int kk0 = kt * 64;
        CP_WAIT0();                    // stage holds fp32 K/V of tile kt
        __syncthreads();               // prior PV readers done; stage visible

        // ---- Convert stage -> hi/lo K,V panels (LDS source) ----
#pragma unroll
        for (int it = 0; it < 8; it++) {
            int idx = tid + it * 256;          // 0..2047
            int r = idx >> 5, c = idx & 31;
            int p = c >> 4;
            uint32_t off = SWZ((uint32_t)(r * 128 + (c & 15) * 8));
            float4 kv = *(const float4*)(fsm + F_ST + r * 512 + c * 16);
            uint2 hi, lo;
            split4(kv, hi, lo);
            *(uint2*)(fsm + F_KH + p * 8192 + off) = hi;
            *(uint2*)(fsm + F_KL + p * 8192 + off) = lo;
            float4 vv = *(const float4*)(fsm + F_ST + 32768 + r * 512 + c * 16);
            split4(vv, hi, lo);
            *(uint2*)(fsm + F_VH + p * 8192 + off) = hi;
            *(uint2*)(fsm + F_VL + p * 8192 + off) = lo;
        }
        __syncthreads();               // panels ready; stage free

        // ---- Prefetch tile kt+1 (overlaps all MMA below) ----
        if (kt + 1 < nkt) fetch_kv(kt + 1);
        CP_COMMIT();

        // ---- S = Q @ K^T (3-pass split; x4-paired K frags) ----
        float s[8][4];
#pragma unroll
        for (int nt = 0; nt < 8; nt++)
#pragma unroll
            for (int j = 0; j < 4; j++) s[nt][j] = 0.0f;

#pragma unroll
        for (int ks = 0; ks < 8; ks++) {
            const int p = ks >> 2;
            uint32_t ah[4], al[4];
            {
                uint32_t kb = (uint32_t)((ks & 3) * 32 + ((lane >> 4) << 4));
                uint32_t aofs = (uint32_t)((wid * 16 + (lane & 15)) * 128) + kb;
                ldsm_x4(ah, sq + F_QH + p * 16384 + SWZ(aofs));
                ldsm_x4(al, sq + F_QL + p * 16384 + SWZ(aofs));
            }
            const uint32_t kb2 = (uint32_t)((ks & 3) * 32 + (((lane >> 3) & 1) << 4));
            const uint32_t rsel = (uint32_t)((lane & 7) + ((lane >> 4) << 3));
#pragma unroll
            for (int ntp = 0; ntp < 4; ntp++) {
                uint32_t bofs = (uint32_t)((ntp * 16 + rsel) * 128) + kb2;
                uint32_t bh4[4], bl4[4];
                ldsm_x4(bh4, sq + F_KH + p * 8192 + SWZ(bofs));
                ldsm_x4(bl4, sq + F_KL + p * 8192 + SWZ(bofs));
                mma16816(s[2 * ntp],     ah, &bh4[0]);
                mma16816(s[2 * ntp],     ah, &bl4[0]);
                mma16816(s[2 * ntp],     al, &bh4[0]);
                mma16816(s[2 * ntp + 1], ah, &bh4[2]);
                mma16816(s[2 * ntp + 1], ah, &bl4[2]);
                mma16816(s[2 * ntp + 1], al, &bh4[2]);
            }
        }

        // ---- Causal mask (only last two tiles can cross the diagonal) ----
        const int rg = q0 + wid * 16 + (lane >> 2);  // row of c0,c1; +8 for c2,c3
        if (kt >= 2 * qt) {
#pragma unroll
            for (int nt = 0; nt < 8; nt++) {
                int col = kk0 + nt * 8 + 2 * (lane & 3);
                if (col > rg)          s[nt][0] = -1e30f;
                if (col + 1 > rg)      s[nt][1] = -1e30f;
                if (col > rg + 8)      s[nt][2] = -1e30f;
                if (col + 1 > rg + 8)  s[nt][3] = -1e30f;
            }
        }

        // ---- Online softmax (rows rg and rg+8; quad-lane reductions) ----
        float mt0 = -1e30f, mt1 = -1e30f;
#pragma unroll
        for (int nt = 0; nt < 8; nt++) {
            mt0 = fmaxf(mt0, fmaxf(s[nt][0], s[nt][1]));
            mt1 = fmaxf(mt1, fmaxf(s[nt][2], s[nt][3]));
        }
        mt0 = fmaxf(mt0, __shfl_xor_sync(0xffffffffu, mt0, 1));
        mt0 = fmaxf(mt0, __shfl_xor_sync(0xffffffffu, mt0, 2));
        mt1 = fmaxf(mt1, __shfl_xor_sync(0xffffffffu, mt1, 1));
        mt1 = fmaxf(mt1, __shfl_xor_sync(0xffffffffu, mt1, 2));

        float mn0 = fmaxf(m0, mt0), mn1 = fmaxf(m1, mt1);
        float a0 = __expf(m0 - mn0), a1 = __expf(m1 - mn1);
        m0 = mn0; m1 = mn1;

        float rs0 = 0.0f, rs1 = 0.0f;
#pragma unroll
        for (int nt = 0; nt < 8; nt++) {
            s[nt][0] = __expf(s[nt][0] - mn0);
            s[nt][1] = __expf(s[nt][1] - mn0);
            s[nt][2] = __expf(s[nt][2] - mn1);
            s[nt][3] = __expf(s[nt][3] - mn1);
            rs0 += s[nt][0] + s[nt][1];
            rs1 += s[nt][2] + s[nt][3];
        }
        rs0 += __shfl_xor_sync(0xffffffffu, rs0, 1);
        rs0 += __shfl_xor_sync(0xffffffffu, rs0, 2);
        rs1 += __shfl_xor_sync(0xffffffffu, rs1, 1);
        rs1 += __shfl_xor_sync(0xffffffffu, rs1, 2);
        l0 = l0 * a0 + rs0;
        l1 = l1 * a1 + rs1;

#pragma unroll
        for (int dt = 0; dt < 16; dt++) {
            o[dt][0] *= a0; o[dt][1] *= a0;
            o[dt][2] *= a1; o[dt][3] *= a1;
        }

        // ---- O += P @ V (P from S regs; x4.trans-paired V frags) ----
#pragma unroll
        for (int ks2 = 0; ks2 < 4; ks2++) {
            const float* t0 = s[2 * ks2];
            const float* t1 = s[2 * ks2 + 1];
            uint32_t ph[4], pl[4];
            ph[0] = pack_bf2(t0[0], t0[1]);
            ph[1] = pack_bf2(t0[2], t0[3]);
            ph[2] = pack_bf2(t1[0], t1[1]);
            ph[3] = pack_bf2(t1[2], t1[3]);
            {
                __nv_bfloat162 hh;
                *reinterpret_cast<uint32_t*>(&hh) = ph[0];
                pl[0] = pack_bf2(t0[0] - __bfloat162float(hh.x), t0[1] - __bfloat162float(hh.y));
                *reinterpret_cast<uint32_t*>(&hh) = ph[1];
                pl[1] = pack_bf2(t0[2] - __bfloat162float(hh.x), t0[3] - __bfloat162float(hh.y));
                *reinterpret_cast<uint32_t*>(&hh) = ph[2];
                pl[2] = pack_bf2(t1[0] - __bfloat162float(hh.x), t1[1] - __bfloat162float(hh.y));
                *reinterpret_cast<uint32_t*>(&hh) = ph[3];
                pl[3] = pack_bf2(t1[2] - __bfloat162float(hh.x), t1[3] - __bfloat162float(hh.y));
            }
            uint32_t vrow = (uint32_t)((ks2 * 16 + (lane & 15)) * 128);
#pragma unroll
            for (int dtp = 0; dtp < 8; dtp++) {
                const int p = dtp >> 2;
                uint32_t colsel = (uint32_t)(((2 * dtp) & 7) + (lane >> 4));
                uint32_t bofs = vrow + colsel * 16;
                uint32_t vh4[4], vl4[4];
                ldsm_x4_t(vh4, sq + F_VH + p * 8192 + SWZ(bofs));
                ldsm_x4_t(vl4, sq + F_VL + p * 8192 + SWZ(bofs));
                mma16816(o[2 * dtp],     ph, &vh4[0]);
                mma16816(o[2 * dtp],     ph, &vl4[0]);
                mma16816(o[2 * dtp],     pl, &vh4[0]);
                mma16816(o[2 * dtp + 1], ph, &vh4[2]);
                mma16816(o[2 * dtp + 1], ph, &vl4[2]);
                mma16816(o[2 * dtp + 1], pl, &vh4[2]);
            }
        }
    }

    // ---- Normalize + write y [B,T,C] (head-interleaved cols) ----
    const float inv0 = 1.0f / l0;
    const float inv1 = 1.0f / l1;
    const int r0 = q0 + wid * 16 + (lane >> 2);
    float* y0 = g_y + ((size_t)b * TT + r0) * CC + (size_t)h * DD;
    float* y1 = g_y + ((size_t)b * TT + r0 + 8) * CC + (size_t)h * DD;
#pragma unroll
    for (int dt = 0; dt < 16; dt++) {
        int col = dt * 8 + 2 * (lane & 3);
        *(float2*)(y0 + col) = make_float2(o[dt][0] * inv0, o[dt][1] * inv0);
        *(float2*)(y1 + col) = make_float2(o[dt][2] * inv1, o[dt][3] * inv1);
    }
}

// ---------------------------------------------------------------------------
// Launch sequence
// ---------------------------------------------------------------------------
extern "C" void kernel_launch(void* const* d_in, const int* in_sizes, int n_in,
                              void* d_out, int out_size)
{
    (void)in_sizes; (void)n_in; (void)out_size;
    const float* x      = (const float*)d_in[0];
    const float* W_attn = (const float*)d_in[1];
    const float* b_attn = (const float*)d_in[2];
    const float* W_proj = (const float*)d_in[3];
    const float* b_proj = (const float*)d_in[4];
    float* out = (float*)d_out;

    float* qkv = nullptr; float* y = nullptr;
    __nv_bfloat16 *ah = nullptr, *al = nullptr, *bh = nullptr, *bl = nullptr;
    cudaGetSymbolAddress((void**)&qkv, g_qkv);
    cudaGetSymbolAddress((void**)&y,   g_y);
    cudaGetSymbolAddress((void**)&ah,  g_ah);
    cudaGetSymbolAddress((void**)&al,  g_al);
    cudaGetSymbolAddress((void**)&bh,  g_bh);
    cudaGetSymbolAddress((void**)&bl,  g_bl);

    cudaFuncSetAttribute(flash_kernel, cudaFuncAttributeMaxDynamicSharedMemorySize,
                         FLASH_SMEM);
    cudaFuncSetAttribute(gemm_mma_kernel, cudaFuncAttributeMaxDynamicSharedMemorySize,
                         (int)G_SMEM);

    const size_t n4 = (size_t)MM * CC / 4;

    // 1) QKV projection: bf16-split mma.sync GEMM (BK=64)
    split_rm_kernel<<<(unsigned)((n4 + 255) / 256), 256>>>(x, ah, al, n4);
    split_tr_kernel<<<dim3(N3 / 32, CC / 32), 256>>>(W_attn, bh, bl, CC, N3);
    gemm_mma_kernel<<<dim3(N3 / 128, MM / 128), 256, G_SMEM>>>(ah, al, bh, bl,
                                                               b_attn, qkv, N3, CC);
    // 2) Causal multi-head attention (tensor-core flash, cp.async staged)
    flash_kernel<<<dim3(TT / 128, HH, BB), 256, FLASH_SMEM>>>();

    // 3) Output projection: bf16-split mma.sync GEMM (BK=64)
    split_rm_kernel<<<(unsigned)((n4 + 255) / 256), 256>>>(y, ah, al, n4);
    split_tr_kernel<<<dim3(CC / 32, CC / 32), 256>>>(W_proj, bh, bl, CC, CC);
    gemm_mma_kernel<<<dim3(CC / 128, MM / 128), 256, G_SMEM>>>(ah, al, bh, bl,
                                                               b_proj, out, CC, CC);
}